// round 11
// baseline (speedup 1.0000x reference)
#include <cuda_runtime.h>
#include <math.h>
#include <stdint.h>

#define BB 64
#define SS 512
#define DD 1024
#define HH 1024
#define GG 4096   // 4*H
#define NBLK 128  // persistent blocks (1/SM via smem)
#define HR 4      // h ring depth

// Scratch (allocation-free rule: __device__ globals)
__device__ float g_xproj[(size_t)BB * SS * GG];  // [B*S, 4H], m = b*S + t (includes bih+bhh)
__device__ float g_h[HR][BB * HH];               // h ring: buffer s%HR = input of step s
__device__ float g_c[BB * HH];                   // cell state
__device__ int g_prod[NBLK];                     // block bx produced h slice through step v-1
__device__ int g_cons[NBLK];                     // block bx staged all chunks through step v-1

__device__ __forceinline__ float sigmoidf_(float x) {
    return 1.0f / (1.0f + expf(-x));
}

__device__ __forceinline__ void cp16(uint32_t s, const void* g) {
    asm volatile("cp.async.cg.shared.global [%0], [%1], 16;\n" :: "r"(s), "l"(g));
}
#define CP_COMMIT() asm volatile("cp.async.commit_group;\n" ::: "memory")
#define CP_WAIT(N)  asm volatile("cp.async.wait_group %0;\n" :: "n"(N) : "memory")

__device__ __forceinline__ int4 ldcg4(const int4* p) {
    int4 v;
    asm volatile("ld.global.cg.v4.u32 {%0,%1,%2,%3}, [%4];"
                 : "=r"(v.x), "=r"(v.y), "=r"(v.z), "=r"(v.w) : "l"(p) : "memory");
    return v;
}
__device__ __forceinline__ int ldcg1(const int* p) {
    int v;
    asm volatile("ld.global.cg.u32 %0, [%1];" : "=r"(v) : "l"(p) : "memory");
    return v;
}
__device__ __forceinline__ void stcg1(int* p, int v) {
    asm volatile("st.global.cg.u32 [%0], %1;" :: "l"(p), "r"(v) : "memory");
}

#define MMA_TF32(C, A, B0, B1)                                               \
    asm volatile(                                                            \
        "mma.sync.aligned.m16n8k8.row.col.f32.tf32.tf32.f32 "                \
        "{%0,%1,%2,%3}, {%4,%5,%6,%7}, {%8,%9}, {%0,%1,%2,%3};\n"            \
        : "+f"((C)[0]), "+f"((C)[1]), "+f"((C)[2]), "+f"((C)[3])             \
        : "r"((A)[0]), "r"((A)[1]), "r"((A)[2]), "r"((A)[3]),                \
          "r"(B0), "r"(B1))

// ---------------------------------------------------------------------------
// init: h0 -> ring buffer 0, c0 -> g_c, reset flags (runs every launch/replay)
// ---------------------------------------------------------------------------
__global__ void init_state(const float* __restrict__ h0, const float* __restrict__ c0) {
    int i = blockIdx.x * blockDim.x + threadIdx.x;
    if (i < BB * HH) {
        g_h[0][i] = h0[i];
        g_c[i]    = c0[i];
    }
    if (i < NBLK) {
        g_prod[i] = 0;
        g_cons[i] = 0;
    }
}

// ---------------------------------------------------------------------------
// xproj (tf32 MMA): C[32768, 4096] = X @ Wih^T + (bih + bhh)
// Block tile 256(M) x 128(N), 512 threads (16 warps), warp tile 64x32.
// ---------------------------------------------------------------------------
#define XBM 256
#define XBN 128
#define XBK 32
#define XSTRIDE 36
#define XA_ELEMS (XBM * XSTRIDE)
#define XB_ELEMS (XBN * XSTRIDE)
#define XSMEM_BYTES ((2 * XA_ELEMS + 2 * XB_ELEMS) * 4)

__global__ __launch_bounds__(512) void xproj_mma(
    const float* __restrict__ X,
    const float* __restrict__ Wih,
    const float* __restrict__ bih,
    const float* __restrict__ bhh)
{
    extern __shared__ float xsm[];
    float* As = xsm;
    float* Bs = xsm + 2 * XA_ELEMS;

    const int m0 = blockIdx.y * XBM;
    const int n0 = blockIdx.x * XBN;
    const int tid = threadIdx.x;
    const int wid = tid >> 5;
    const int lane = tid & 31;
    const int gid = lane >> 2;
    const int tg  = lane & 3;
    const int wm = wid & 3;      // m 64-rows
    const int wn = wid >> 2;     // n 32-cols

    const uint32_t As_s = (uint32_t)__cvta_generic_to_shared(As);
    const uint32_t Bs_s = (uint32_t)__cvta_generic_to_shared(Bs);

    auto load_tiles = [&](int k0, int buf) {
#pragma unroll
        for (int i = 0; i < 4; i++) {             // A: 256x32 -> 2048 units
            int u = tid + i * 512;
            int r = u >> 3;
            int c4 = (u & 7) * 4;
            cp16(As_s + (uint32_t)(buf * XA_ELEMS + r * XSTRIDE + c4) * 4,
                 X + (size_t)(m0 + r) * DD + k0 + c4);
        }
#pragma unroll
        for (int i = 0; i < 2; i++) {             // B: 128x32 -> 1024 units
            int u = tid + i * 512;
            int r = u >> 3;
            int c4 = (u & 7) * 4;
            cp16(Bs_s + (uint32_t)(buf * XB_ELEMS + r * XSTRIDE + c4) * 4,
                 Wih + (size_t)(n0 + r) * DD + k0 + c4);
        }
    };

    float acc[4][4][4];
#pragma unroll
    for (int a = 0; a < 4; a++)
#pragma unroll
        for (int b = 0; b < 4; b++)
#pragma unroll
            for (int c = 0; c < 4; c++) acc[a][b][c] = 0.0f;

    load_tiles(0, 0);
    CP_COMMIT();

#pragma unroll 1
    for (int kc = 0; kc < DD / XBK; kc++) {
        int cur = kc & 1;
        if (kc + 1 < DD / XBK) {
            load_tiles((kc + 1) * XBK, cur ^ 1);
            CP_COMMIT();
            CP_WAIT(1);
        } else {
            CP_WAIT(0);
        }
        __syncthreads();

        const float* ab = As + cur * XA_ELEMS;
        const float* bb = Bs + cur * XB_ELEMS;

#pragma unroll
        for (int ks = 0; ks < 4; ks++) {
            int kb = ks * 8;
            uint32_t af[4][4];
#pragma unroll
            for (int mi = 0; mi < 4; mi++) {
                int row = wm * 64 + mi * 16 + gid;
                af[mi][0] = __float_as_uint(ab[row * XSTRIDE + kb + tg]);
                af[mi][1] = __float_as_uint(ab[(row + 8) * XSTRIDE + kb + tg]);
                af[mi][2] = __float_as_uint(ab[row * XSTRIDE + kb + tg + 4]);
                af[mi][3] = __float_as_uint(ab[(row + 8) * XSTRIDE + kb + tg + 4]);
            }
#pragma unroll
            for (int ni = 0; ni < 4; ni++) {
                int nrow = wn * 32 + ni * 8 + gid;
                uint32_t b0 = __float_as_uint(bb[nrow * XSTRIDE + kb + tg]);
                uint32_t b1 = __float_as_uint(bb[nrow * XSTRIDE + kb + tg + 4]);
#pragma unroll
                for (int mi = 0; mi < 4; mi++) MMA_TF32(acc[mi][ni], af[mi], b0, b1);
            }
        }
        __syncthreads();
    }

#pragma unroll
    for (int ni = 0; ni < 4; ni++) {
        int n = n0 + wn * 32 + ni * 8 + tg * 2;
        float bv0 = bih[n] + bhh[n];
        float bv1 = bih[n + 1] + bhh[n + 1];
#pragma unroll
        for (int mi = 0; mi < 4; mi++) {
            int m = m0 + wm * 64 + mi * 16 + gid;
            float2 v0 = make_float2(acc[mi][ni][0] + bv0, acc[mi][ni][1] + bv1);
            *(float2*)(g_xproj + (size_t)m * GG + n) = v0;
            float2 v1 = make_float2(acc[mi][ni][2] + bv0, acc[mi][ni][3] + bv1);
            *(float2*)(g_xproj + (size_t)(m + 8) * GG + n) = v1;
        }
    }
}

// ---------------------------------------------------------------------------
// Persistent LSTM, dataflow-synced (no grid barrier).
// 128 blocks, 1/SM, 512 threads (16 warps).
// Block bx: j-cols [bx*8, bx*8+8), all 64 batches, 4 gates (32 Whh rows).
// Warps: mw = wid&1 (32-batch half), kh = wid>>1 (16-col k-slice per chunk).
// h streamed in 8 contiguous 128-col chunks from a 4-deep ring; chunk c is
// produced by blocks 16c..16c+15 (flags g_prod); block rotates chunk order
// starting at its own group. Staging completion posted via g_cons; a producer
// overwrites a ring slot only after all blocks consumed it (3-step slack).
// ---------------------------------------------------------------------------
#define WS_STRIDE 1028                 // 1024+4 -> conflict-free (stride 4 mod 32)
#define WS_TOT (32 * WS_STRIDE)        // 32896 floats
#define NCH 8
#define HS_STRIDE 132
#define HS_ELEMS (64 * HS_STRIDE)      // 8448 floats per buffer
#define GSLAB (4 * 64 * 8)             // 2048 floats per K-slab
#define PSMEM_FLOATS (WS_TOT + 2 * HS_ELEMS + 512)
#define PSMEM_BYTES (PSMEM_FLOATS * 4)  // 201,216 B  (gsm aliases hs)

__global__ __launch_bounds__(512, 1) void lstm_persist(
    const float* __restrict__ Whh,
    float* __restrict__ out)
{
    extern __shared__ float sm[];
    float* ws  = sm;                         // [32][WS_STRIDE] weights (persistent)
    float* hs  = ws + WS_TOT;                // [2][64][HS_STRIDE] h chunk staging
    float* gsm = hs;                         // [8][4][64][8] partials (ALIAS, epilogue only)
    float* csm = hs + 2 * HS_ELEMS;          // [512] cell slice (persistent)

    const int bx  = blockIdx.x;
    const int j0  = bx * 8;
    const int tid = threadIdx.x;
    const int wid = tid >> 5;
    const int lane = tid & 31;
    const int gid = lane >> 2;
    const int tg  = lane & 3;
    const int mw = wid & 1;            // batch half (32 rows)
    const int kh = wid >> 1;           // 16-col k-slice within a staged chunk
    const int my_grp = bx >> 4;        // this block's chunk group

    const uint32_t ws_s = (uint32_t)__cvta_generic_to_shared(ws);
    const uint32_t hs_s = (uint32_t)__cvta_generic_to_shared(hs);

    // ---- one-time: load Whh slice (32 rows x 1024) into SMEM ----
#pragma unroll 4
    for (int i = 0; i < 16; i++) {
        int u = tid + i * 512;               // 0..8191 16B-units
        int r = u >> 8;                      // row = g*8 + jj
        int c4 = (u & 255) * 4;
        int n = (r >> 3) * HH + j0 + (r & 7);
        cp16(ws_s + (uint32_t)(r * WS_STRIDE + c4) * 4, Whh + (size_t)n * HH + c4);
    }
    CP_COMMIT();

    // ---- loader addresses: chunk = contiguous 128 h-cols ----
    int ld_goff[4];      // row*HH + col ; add ord*128 per chunk
    uint32_t ld_soff[4]; // byte offset inside one hs buffer
#pragma unroll
    for (int i = 0; i < 4; i++) {
        int u = tid + i * 512;
        int row = u >> 5;
        int c4 = (u & 31) * 4;
        ld_goff[i] = row * HH + c4;
        ld_soff[i] = (uint32_t)(row * HS_STRIDE + c4) * 4;
    }

    // ---- one-time: cell slice + epilogue indices (1 elem/thread) ----
    const int b_e  = tid >> 3;
    const int jj_e = tid & 7;
    const int nj_e = j0 + jj_e;
    const size_t xb_e = (size_t)b_e * SS * GG + nj_e;
    const size_t ob_e = (size_t)b_e * SS * HH + nj_e;
    csm[tid] = g_c[b_e * HH + nj_e];
    CP_WAIT(0);
    __syncthreads();

    // weight row pointers: per chunk add ord*128 + ks*8
    const float* wptr[4];
#pragma unroll
    for (int g = 0; g < 4; g++)
        wptr[g] = ws + (size_t)(g * 8 + gid) * WS_STRIDE + kh * 16 + tg;

    const int arow0 = mw * 32 + gid;   // A rows: arow0, +8, +16, +24
    const int kloc = kh * 16;          // warp's col base within a staged chunk

    // poll: wait until the 16 producers of chunk `c` reached step t
    auto poll_chunk = [&](int c, int t) {
        const int4* p = (const int4*)(g_prod + c * 16);
        for (;;) {
            int4 a = ldcg4(p), b = ldcg4(p + 1), d = ldcg4(p + 2), e = ldcg4(p + 3);
            int m1 = min(min(a.x, a.y), min(a.z, a.w));
            int m2 = min(min(b.x, b.y), min(b.z, b.w));
            int m3 = min(min(d.x, d.y), min(d.z, d.w));
            int m4 = min(min(e.x, e.y), min(e.z, e.w));
            if (min(min(m1, m2), min(m3, m4)) >= t) break;
            __nanosleep(64);
        }
    };

#pragma unroll 1
    for (int t = 0; t < SS; t++) {
        const float* __restrict__ h_in = g_h[t & (HR - 1)];
        float* __restrict__ h_out = g_h[(t + 1) & (HR - 1)];

        // issue first chunk (own group)
        {
            int ord0 = my_grp;
            poll_chunk(ord0, t);
            int goff = ord0 * 128;
#pragma unroll
            for (int i = 0; i < 4; i++)
                cp16(hs_s + ld_soff[i], h_in + ld_goff[i] + goff);
        }
        CP_COMMIT();

        // prefetch xproj gate tile for (block, t)
        float xp[4];
#pragma unroll
        for (int g = 0; g < 4; g++)
            xp[g] = __ldg(&g_xproj[xb_e + (size_t)t * GG + g * HH]);

        float acc0[4][4], acc1[4][4];
#pragma unroll
        for (int g = 0; g < 4; g++)
#pragma unroll
            for (int r = 0; r < 4; r++) { acc0[g][r] = 0.f; acc1[g][r] = 0.f; }

#pragma unroll 1
        for (int i = 0; i < NCH; i++) {
            const int ord = (my_grp + i) & 7;
            CP_WAIT(0);
            __syncthreads();
            if (i == NCH - 1 && tid == 0)       // all staging for step t complete
                stcg1(g_cons + bx, t + 1);
            if (i + 1 < NCH) {
                int ordn = (my_grp + i + 1) & 7;
                poll_chunk(ordn, t);
                uint32_t base = hs_s + (uint32_t)(((i + 1) & 1) * HS_ELEMS) * 4;
                int goff = ordn * 128;
#pragma unroll
                for (int k = 0; k < 4; k++)
                    cp16(base + ld_soff[k], h_in + ld_goff[k] + goff);
                CP_COMMIT();
            }

            const float* hb = hs + (i & 1) * HS_ELEMS;
            const int kwofs = ord * 128;       // weight col offset for this chunk

#pragma unroll
            for (int ks = 0; ks < 2; ks++) {
                int kb = kloc + ks * 8;
                uint32_t a0[4], a1[4];
                a0[0] = __float_as_uint(hb[(arow0)      * HS_STRIDE + kb + tg]);
                a0[1] = __float_as_uint(hb[(arow0 + 8)  * HS_STRIDE + kb + tg]);
                a0[2] = __float_as_uint(hb[(arow0)      * HS_STRIDE + kb + tg + 4]);
                a0[3] = __float_as_uint(hb[(arow0 + 8)  * HS_STRIDE + kb + tg + 4]);
                a1[0] = __float_as_uint(hb[(arow0 + 16) * HS_STRIDE + kb + tg]);
                a1[1] = __float_as_uint(hb[(arow0 + 24) * HS_STRIDE + kb + tg]);
                a1[2] = __float_as_uint(hb[(arow0 + 16) * HS_STRIDE + kb + tg + 4]);
                a1[3] = __float_as_uint(hb[(arow0 + 24) * HS_STRIDE + kb + tg + 4]);

#pragma unroll
                for (int g = 0; g < 4; g++) {
                    uint32_t b0 = __float_as_uint(wptr[g][kwofs + ks * 8]);
                    uint32_t b1 = __float_as_uint(wptr[g][kwofs + ks * 8 + 4]);
                    MMA_TF32(acc0[g], a0, b0, b1);
                    MMA_TF32(acc1[g], a1, b0, b1);
                }
            }
        }

        // all compute done before gsm (aliased over hs) is written
        __syncthreads();

        // stash partials: gsm[kh][g][batch][jj]
        {
            float* gs = gsm + kh * GSLAB;
            int r0 = mw * 32 + gid;
#pragma unroll
            for (int g = 0; g < 4; g++) {
                gs[(g * 64 + r0)      * 8 + tg * 2 + 0] = acc0[g][0];
                gs[(g * 64 + r0)      * 8 + tg * 2 + 1] = acc0[g][1];
                gs[(g * 64 + r0 + 8)  * 8 + tg * 2 + 0] = acc0[g][2];
                gs[(g * 64 + r0 + 8)  * 8 + tg * 2 + 1] = acc0[g][3];
                gs[(g * 64 + r0 + 16) * 8 + tg * 2 + 0] = acc1[g][0];
                gs[(g * 64 + r0 + 16) * 8 + tg * 2 + 1] = acc1[g][1];
                gs[(g * 64 + r0 + 24) * 8 + tg * 2 + 0] = acc1[g][2];
                gs[(g * 64 + r0 + 24) * 8 + tg * 2 + 1] = acc1[g][3];
            }
        }
        __syncthreads();

        // fused cell update (1 element/thread; reduce 8 K-slabs)
        float hval;
        {
            int base = b_e * 8 + jj_e;
            float gv4[4];
#pragma unroll
            for (int g = 0; g < 4; g++) {
                float s = xp[g];
#pragma unroll
                for (int sl = 0; sl < 8; sl++)
                    s += gsm[sl * GSLAB + (g * 64) * 8 + base];
                gv4[g] = s;
            }

            float iv = sigmoidf_(gv4[0]);
            float fv = sigmoidf_(gv4[1]);
            float gv = tanhf(gv4[2]);
            float ov = sigmoidf_(gv4[3]);

            float cc = fv * csm[tid] + iv * gv;
            csm[tid] = cc;
            hval = ov * tanhf(cc);
            out[ob_e + (size_t)t * HH] = hval;   // no hazard, write immediately
        }

        // producer wait: ring slot (t+1)%HR previously held input of step
        // t+1-HR; all blocks must have fully staged that step (cons >= t+2-HR).
        if (t >= HR - 1) {
            const int need = t + 2 - HR;
            for (;;) {
                int v = (tid < NBLK) ? ldcg1(g_cons + tid) : need;
                if (__syncthreads_and(v >= need)) break;
                __nanosleep(64);
            }
        }

        // publish h slice for step t
        h_out[b_e * HH + nj_e] = hval;
        __syncthreads();
        if (tid == 0) {
            __threadfence();
            stcg1(g_prod + bx, t + 1);
        }
    }

    // write back cell state
    g_c[b_e * HH + nj_e] = csm[tid];
}

// ---------------------------------------------------------------------------
// tail: hn then cn after outputs. Final h = output of step 511 = ring buf 0.
// ---------------------------------------------------------------------------
__global__ void write_final(float* __restrict__ tail) {
    int i = blockIdx.x * blockDim.x + threadIdx.x;
    if (i < BB * HH) {
        tail[i] = g_h[SS & (HR - 1)][i];
        tail[BB * HH + i] = g_c[i];
    }
}

// ---------------------------------------------------------------------------
extern "C" void kernel_launch(void* const* d_in, const int* in_sizes, int n_in,
                              void* d_out, int out_size) {
    const float* X   = (const float*)d_in[0];  // [B,S,D]
    const float* h0  = (const float*)d_in[1];  // [1,B,H]
    const float* c0  = (const float*)d_in[2];  // [1,B,H]
    const float* Wih = (const float*)d_in[3];  // [4H,D]
    const float* Whh = (const float*)d_in[4];  // [4H,H]
    const float* bih = (const float*)d_in[5];  // [4H]
    const float* bhh = (const float*)d_in[6];  // [4H]
    float* out = (float*)d_out;                // outputs [B,S,H] | hn | cn

    cudaFuncSetAttribute(xproj_mma,
                         cudaFuncAttributeMaxDynamicSharedMemorySize, XSMEM_BYTES);
    cudaFuncSetAttribute(lstm_persist,
                         cudaFuncAttributeMaxDynamicSharedMemorySize, PSMEM_BYTES);

    init_state<<<(BB * HH + 255) / 256, 256>>>(h0, c0);

    dim3 gx(GG / XBN, (BB * SS) / XBM);
    xproj_mma<<<gx, 512, XSMEM_BYTES>>>(X, Wih, bih, bhh);

    lstm_persist<<<NBLK, 512, PSMEM_BYTES>>>(Whh, out);

    write_final<<<(BB * HH + 255) / 256, 256>>>(out + (size_t)BB * SS * HH);
}

// round 12
// speedup vs baseline: 2.2842x; 2.2842x over previous
#include <cuda_runtime.h>
#include <math.h>
#include <stdint.h>

#define BB 64
#define SS 512
#define DD 1024
#define HH 1024
#define GG 4096   // 4*H
#define NBLK 128  // persistent blocks (1/SM via smem)

// Scratch (allocation-free rule: __device__ globals)
__device__ float g_xproj[(size_t)BB * SS * GG];  // [B*S, 4H], m = b*S + t (includes bih+bhh)
__device__ float g_h[2][BB * HH];                // ping-pong hidden state
__device__ float g_c[BB * HH];                   // cell state
__device__ int g_arr[NBLK];                      // distributed barrier flags (monotonic)

__device__ __forceinline__ float sigmoidf_(float x) {
    return 1.0f / (1.0f + expf(-x));
}

__device__ __forceinline__ void cp16(uint32_t s, const void* g) {
    asm volatile("cp.async.cg.shared.global [%0], [%1], 16;\n" :: "r"(s), "l"(g));
}
#define CP_COMMIT() asm volatile("cp.async.commit_group;\n" ::: "memory")
#define CP_WAIT(N)  asm volatile("cp.async.wait_group %0;\n" :: "n"(N) : "memory")

__device__ __forceinline__ int4 ldcg4(const int4* p) {
    int4 v;
    asm volatile("ld.global.cg.v4.u32 {%0,%1,%2,%3}, [%4];"
                 : "=r"(v.x), "=r"(v.y), "=r"(v.z), "=r"(v.w) : "l"(p) : "memory");
    return v;
}
__device__ __forceinline__ void stcg1(int* p, int v) {
    asm volatile("st.global.cg.u32 [%0], %1;" :: "l"(p), "r"(v) : "memory");
}

#define MMA_TF32(C, A, B0, B1)                                               \
    asm volatile(                                                            \
        "mma.sync.aligned.m16n8k8.row.col.f32.tf32.tf32.f32 "                \
        "{%0,%1,%2,%3}, {%4,%5,%6,%7}, {%8,%9}, {%0,%1,%2,%3};\n"            \
        : "+f"((C)[0]), "+f"((C)[1]), "+f"((C)[2]), "+f"((C)[3])             \
        : "r"((A)[0]), "r"((A)[1]), "r"((A)[2]), "r"((A)[3]),                \
          "r"(B0), "r"(B1))

// ---------------------------------------------------------------------------
__global__ void init_state(const float* __restrict__ h0, const float* __restrict__ c0) {
    int i = blockIdx.x * blockDim.x + threadIdx.x;
    if (i < BB * HH) {
        g_h[0][i] = h0[i];
        g_c[i]    = c0[i];
    }
    if (i < NBLK) g_arr[i] = 0;
}

// ---------------------------------------------------------------------------
// xproj (tf32 MMA): C[32768, 4096] = X @ Wih^T + (bih + bhh)
// Block tile 256(M) x 128(N), 512 threads (16 warps), warp tile 64x32.
// ---------------------------------------------------------------------------
#define XBM 256
#define XBN 128
#define XBK 32
#define XSTRIDE 36
#define XA_ELEMS (XBM * XSTRIDE)
#define XB_ELEMS (XBN * XSTRIDE)
#define XSMEM_BYTES ((2 * XA_ELEMS + 2 * XB_ELEMS) * 4)

__global__ __launch_bounds__(512) void xproj_mma(
    const float* __restrict__ X,
    const float* __restrict__ Wih,
    const float* __restrict__ bih,
    const float* __restrict__ bhh)
{
    extern __shared__ float xsm[];
    float* As = xsm;
    float* Bs = xsm + 2 * XA_ELEMS;

    const int m0 = blockIdx.y * XBM;
    const int n0 = blockIdx.x * XBN;
    const int tid = threadIdx.x;
    const int wid = tid >> 5;
    const int lane = tid & 31;
    const int gid = lane >> 2;
    const int tg  = lane & 3;
    const int wm = wid & 3;      // m 64-rows
    const int wn = wid >> 2;     // n 32-cols

    const uint32_t As_s = (uint32_t)__cvta_generic_to_shared(As);
    const uint32_t Bs_s = (uint32_t)__cvta_generic_to_shared(Bs);

    auto load_tiles = [&](int k0, int buf) {
#pragma unroll
        for (int i = 0; i < 4; i++) {             // A: 256x32 -> 2048 units
            int u = tid + i * 512;
            int r = u >> 3;
            int c4 = (u & 7) * 4;
            cp16(As_s + (uint32_t)(buf * XA_ELEMS + r * XSTRIDE + c4) * 4,
                 X + (size_t)(m0 + r) * DD + k0 + c4);
        }
#pragma unroll
        for (int i = 0; i < 2; i++) {             // B: 128x32 -> 1024 units
            int u = tid + i * 512;
            int r = u >> 3;
            int c4 = (u & 7) * 4;
            cp16(Bs_s + (uint32_t)(buf * XB_ELEMS + r * XSTRIDE + c4) * 4,
                 Wih + (size_t)(n0 + r) * DD + k0 + c4);
        }
    };

    float acc[4][4][4];
#pragma unroll
    for (int a = 0; a < 4; a++)
#pragma unroll
        for (int b = 0; b < 4; b++)
#pragma unroll
            for (int c = 0; c < 4; c++) acc[a][b][c] = 0.0f;

    load_tiles(0, 0);
    CP_COMMIT();

#pragma unroll 1
    for (int kc = 0; kc < DD / XBK; kc++) {
        int cur = kc & 1;
        if (kc + 1 < DD / XBK) {
            load_tiles((kc + 1) * XBK, cur ^ 1);
            CP_COMMIT();
            CP_WAIT(1);
        } else {
            CP_WAIT(0);
        }
        __syncthreads();

        const float* ab = As + cur * XA_ELEMS;
        const float* bb = Bs + cur * XB_ELEMS;

#pragma unroll
        for (int ks = 0; ks < 4; ks++) {
            int kb = ks * 8;
            uint32_t af[4][4];
#pragma unroll
            for (int mi = 0; mi < 4; mi++) {
                int row = wm * 64 + mi * 16 + gid;
                af[mi][0] = __float_as_uint(ab[row * XSTRIDE + kb + tg]);
                af[mi][1] = __float_as_uint(ab[(row + 8) * XSTRIDE + kb + tg]);
                af[mi][2] = __float_as_uint(ab[row * XSTRIDE + kb + tg + 4]);
                af[mi][3] = __float_as_uint(ab[(row + 8) * XSTRIDE + kb + tg + 4]);
            }
#pragma unroll
            for (int ni = 0; ni < 4; ni++) {
                int nrow = wn * 32 + ni * 8 + gid;
                uint32_t b0 = __float_as_uint(bb[nrow * XSTRIDE + kb + tg]);
                uint32_t b1 = __float_as_uint(bb[nrow * XSTRIDE + kb + tg + 4]);
#pragma unroll
                for (int mi = 0; mi < 4; mi++) MMA_TF32(acc[mi][ni], af[mi], b0, b1);
            }
        }
        __syncthreads();
    }

#pragma unroll
    for (int ni = 0; ni < 4; ni++) {
        int n = n0 + wn * 32 + ni * 8 + tg * 2;
        float bv0 = bih[n] + bhh[n];
        float bv1 = bih[n + 1] + bhh[n + 1];
#pragma unroll
        for (int mi = 0; mi < 4; mi++) {
            int m = m0 + wm * 64 + mi * 16 + gid;
            float2 v0 = make_float2(acc[mi][ni][0] + bv0, acc[mi][ni][1] + bv1);
            *(float2*)(g_xproj + (size_t)m * GG + n) = v0;
            float2 v1 = make_float2(acc[mi][ni][2] + bv0, acc[mi][ni][3] + bv1);
            *(float2*)(g_xproj + (size_t)(m + 8) * GG + n) = v1;
        }
    }
}

// ---------------------------------------------------------------------------
// Persistent LSTM. 128 blocks, 1/SM, 512 threads (16 warps).
// Block bx: j-cols [bx*8, bx*8+8), all 64 batches, 4 gates (32 Whh rows).
// Warp (mw = wid&1, kh = wid>>1): rows mw*32..+31, k-slice kh*16 per chunk.
// Each warp streams ITS OWN h slice (32 rows x 16 cols per chunk, 8 chunks)
// through a private double-buffered SMEM tile via its own cp.async groups —
// NO block-wide syncs in the K loop (cp.async.wait_group + __syncwarp only).
// Partial sums in 8 SMEM slabs (aliased onto staging), fused epilogue,
// distributed flag barrier (store + warp-parallel poll; no atomic funnel).
// ---------------------------------------------------------------------------
#define WS_STRIDE 1028                 // 1024+4: (g*8+gid)*1028 -> 4*gid mod 32, conflict-free
#define WS_TOT (32 * WS_STRIDE)        // 32896 floats (128.5 KB)
#define NCH 8
#define HSTG_STRIDE 20                 // 16 cols + 4 pad: gid*20+tg -> 32 distinct banks
#define HSTG_BUF (32 * HSTG_STRIDE)    // 640 floats per warp-buffer
#define HSTG_WARP (2 * HSTG_BUF)       // 1280 floats (double buffered)
#define HSTG_TOT (16 * HSTG_WARP)      // 20480 floats (80 KB)
#define GSLAB (4 * 64 * 8)             // 2048 floats per K-slab (8 slabs alias staging)
#define PSMEM_FLOATS (WS_TOT + HSTG_TOT + 512)
#define PSMEM_BYTES (PSMEM_FLOATS * 4) // 215,552 B

__global__ __launch_bounds__(512, 1) void lstm_persist(
    const float* __restrict__ Whh,
    float* __restrict__ out)
{
    extern __shared__ float sm[];
    float* ws   = sm;                        // [32][WS_STRIDE] weights (persistent)
    float* hstg = ws + WS_TOT;               // [16][2][640] per-warp staging
    float* gsm  = hstg;                      // [8][4][64][8] partials (ALIAS, epilogue only)
    float* csm  = hstg + HSTG_TOT;           // [512] cell slice (persistent)

    const int bx  = blockIdx.x;
    const int j0  = bx * 8;
    const int tid = threadIdx.x;
    const int wid = tid >> 5;
    const int lane = tid & 31;
    const int gid = lane >> 2;
    const int tg  = lane & 3;
    const int mw = wid & 1;            // batch half (32 rows)
    const int kh = wid >> 1;           // 16-col k-slice index

    const uint32_t ws_s = (uint32_t)__cvta_generic_to_shared(ws);
    float* mystg = hstg + wid * HSTG_WARP;
    const uint32_t mystg_s = (uint32_t)__cvta_generic_to_shared(mystg);

    // ---- one-time: load Whh slice (32 rows x 1024) into SMEM ----
#pragma unroll 4
    for (int i = 0; i < 16; i++) {
        int u = tid + i * 512;               // 0..8191 16B-units
        int r = u >> 8;                      // row = g*8 + jj
        int c4 = (u & 255) * 4;
        int n = (r >> 3) * HH + j0 + (r & 7);
        cp16(ws_s + (uint32_t)(r * WS_STRIDE + c4) * 4, Whh + (size_t)n * HH + c4);
    }
    CP_COMMIT();

    // ---- per-lane staging addresses (4 cp16 per chunk) ----
    // unit u = lane + 32*i: local row = u>>2 (0..31), col4 = (u&3)*4 (0,4,8,12)
    int ld_goff[4];      // global: (mw*32+row)*HH + kh*16 + col4 ; add chunk*128
    uint32_t ld_soff[4]; // bytes into one warp staging buffer
#pragma unroll
    for (int i = 0; i < 4; i++) {
        int u = lane + i * 32;
        int row = u >> 2;
        int c4 = (u & 3) * 4;
        ld_goff[i] = (mw * 32 + row) * HH + kh * 16 + c4;
        ld_soff[i] = (uint32_t)(row * HSTG_STRIDE + c4) * 4;
    }

    // ---- one-time: cell slice + epilogue indices (1 elem/thread) ----
    const int b_e  = tid >> 3;
    const int jj_e = tid & 7;
    const int nj_e = j0 + jj_e;
    const size_t xb_e = (size_t)b_e * SS * GG + nj_e;
    const size_t ob_e = (size_t)b_e * SS * HH + nj_e;
    csm[tid] = g_c[b_e * HH + nj_e];
    CP_WAIT(0);
    __syncthreads();

    // weight row pointers: per chunk add c*128, plus ks*8 / +4
    const float* wptr[4];
#pragma unroll
    for (int g = 0; g < 4; g++)
        wptr[g] = ws + (size_t)(g * 8 + gid) * WS_STRIDE + kh * 16 + tg;

#pragma unroll 1
    for (int t = 0; t < SS; t++) {
        const float* __restrict__ h_in = g_h[t & 1];
        float* __restrict__ h_out = g_h[(t + 1) & 1];

        // prefetch xproj gate tile for (block, t)
        float xp[4];
#pragma unroll
        for (int g = 0; g < 4; g++)
            xp[g] = __ldg(&g_xproj[xb_e + (size_t)t * GG + g * HH]);

        // issue chunk 0 (per-warp, private buffer 0)
#pragma unroll
        for (int i = 0; i < 4; i++)
            cp16(mystg_s + ld_soff[i], h_in + ld_goff[i]);
        CP_COMMIT();

        float acc0[4][4], acc1[4][4];
#pragma unroll
        for (int g = 0; g < 4; g++)
#pragma unroll
            for (int r = 0; r < 4; r++) { acc0[g][r] = 0.f; acc1[g][r] = 0.f; }

#pragma unroll 1
        for (int c = 0; c < NCH; c++) {
            if (c + 1 < NCH) {
                uint32_t base = mystg_s + (uint32_t)(((c + 1) & 1) * HSTG_BUF) * 4;
                int goff = (c + 1) * 128;
#pragma unroll
                for (int i = 0; i < 4; i++)
                    cp16(base + ld_soff[i], h_in + ld_goff[i] + goff);
                CP_COMMIT();
                CP_WAIT(1);
            } else {
                CP_WAIT(0);
            }
            __syncwarp();

            const float* hb = mystg + (c & 1) * HSTG_BUF;
            const int kwofs = c * 128;         // weight col offset for this chunk

#pragma unroll
            for (int ks = 0; ks < 2; ks++) {
                int kb = ks * 8 + tg;
                uint32_t a0[4], a1[4];
                a0[0] = __float_as_uint(hb[(gid)      * HSTG_STRIDE + kb]);
                a0[1] = __float_as_uint(hb[(gid + 8)  * HSTG_STRIDE + kb]);
                a0[2] = __float_as_uint(hb[(gid)      * HSTG_STRIDE + kb + 4]);
                a0[3] = __float_as_uint(hb[(gid + 8)  * HSTG_STRIDE + kb + 4]);
                a1[0] = __float_as_uint(hb[(gid + 16) * HSTG_STRIDE + kb]);
                a1[1] = __float_as_uint(hb[(gid + 24) * HSTG_STRIDE + kb]);
                a1[2] = __float_as_uint(hb[(gid + 16) * HSTG_STRIDE + kb + 4]);
                a1[3] = __float_as_uint(hb[(gid + 24) * HSTG_STRIDE + kb + 4]);

#pragma unroll
                for (int g = 0; g < 4; g++) {
                    uint32_t b0 = __float_as_uint(wptr[g][kwofs + ks * 8]);
                    uint32_t b1 = __float_as_uint(wptr[g][kwofs + ks * 8 + 4]);
                    MMA_TF32(acc0[g], a0, b0, b1);
                    MMA_TF32(acc1[g], a1, b0, b1);
                }
            }
            __syncwarp();   // all lanes done reading buffer before next overwrite
        }

        // all warps done computing before gsm (aliased over staging) is written
        __syncthreads();

        // stash partials: gsm[kh][g][batch][jj]
        {
            float* gs = gsm + kh * GSLAB;
            int r0 = mw * 32 + gid;
#pragma unroll
            for (int g = 0; g < 4; g++) {
                gs[(g * 64 + r0)      * 8 + tg * 2 + 0] = acc0[g][0];
                gs[(g * 64 + r0)      * 8 + tg * 2 + 1] = acc0[g][1];
                gs[(g * 64 + r0 + 8)  * 8 + tg * 2 + 0] = acc0[g][2];
                gs[(g * 64 + r0 + 8)  * 8 + tg * 2 + 1] = acc0[g][3];
                gs[(g * 64 + r0 + 16) * 8 + tg * 2 + 0] = acc1[g][0];
                gs[(g * 64 + r0 + 16) * 8 + tg * 2 + 1] = acc1[g][1];
                gs[(g * 64 + r0 + 24) * 8 + tg * 2 + 0] = acc1[g][2];
                gs[(g * 64 + r0 + 24) * 8 + tg * 2 + 1] = acc1[g][3];
            }
        }
        __syncthreads();

        // fused cell update (1 element/thread; reduce 8 K-slabs)
        {
            int base = b_e * 8 + jj_e;
            float gv4[4];
#pragma unroll
            for (int g = 0; g < 4; g++) {
                float s = xp[g];
#pragma unroll
                for (int sl = 0; sl < 8; sl++)
                    s += gsm[sl * GSLAB + (g * 64) * 8 + base];
                gv4[g] = s;
            }

            float iv = sigmoidf_(gv4[0]);
            float fv = sigmoidf_(gv4[1]);
            float gv = tanhf(gv4[2]);
            float ov = sigmoidf_(gv4[3]);

            float cc = fv * csm[tid] + iv * gv;
            csm[tid] = cc;
            float h = ov * tanhf(cc);
            h_out[b_e * HH + nj_e] = h;
            out[ob_e + (size_t)t * HH] = h;
        }

        // ---- distributed barrier: store own flag, warp 0 polls all 128 ----
        __syncthreads();                      // h publish complete (block-wide)
        if (tid == 0) {
            __threadfence();
            stcg1(g_arr + bx, t + 1);
        }
        if (wid == 0) {
            const int4* p = (const int4*)g_arr + lane;  // 32 lanes x 4 flags
            for (;;) {
                int4 v = ldcg4(p);
                bool ok = min(min(v.x, v.y), min(v.z, v.w)) >= t + 1;
                if (__all_sync(0xffffffffu, ok)) break;
                __nanosleep(32);
            }
        }
        __syncthreads();
    }

    // write back cell state
    g_c[b_e * HH + nj_e] = csm[tid];
}

// ---------------------------------------------------------------------------
// tail: hn then cn after outputs. Final h = output of step 511 -> buffer 0.
// ---------------------------------------------------------------------------
__global__ void write_final(float* __restrict__ tail) {
    int i = blockIdx.x * blockDim.x + threadIdx.x;
    if (i < BB * HH) {
        tail[i] = g_h[SS & 1][i];
        tail[BB * HH + i] = g_c[i];
    }
}

// ---------------------------------------------------------------------------
extern "C" void kernel_launch(void* const* d_in, const int* in_sizes, int n_in,
                              void* d_out, int out_size) {
    const float* X   = (const float*)d_in[0];  // [B,S,D]
    const float* h0  = (const float*)d_in[1];  // [1,B,H]
    const float* c0  = (const float*)d_in[2];  // [1,B,H]
    const float* Wih = (const float*)d_in[3];  // [4H,D]
    const float* Whh = (const float*)d_in[4];  // [4H,H]
    const float* bih = (const float*)d_in[5];  // [4H]
    const float* bhh = (const float*)d_in[6];  // [4H]
    float* out = (float*)d_out;                // outputs [B,S,H] | hn | cn

    cudaFuncSetAttribute(xproj_mma,
                         cudaFuncAttributeMaxDynamicSharedMemorySize, XSMEM_BYTES);
    cudaFuncSetAttribute(lstm_persist,
                         cudaFuncAttributeMaxDynamicSharedMemorySize, PSMEM_BYTES);

    init_state<<<(BB * HH + 255) / 256, 256>>>(h0, c0);

    dim3 gx(GG / XBN, (BB * SS) / XBM);
    xproj_mma<<<gx, 512, XSMEM_BYTES>>>(X, Wih, bih, bhh);

    lstm_persist<<<NBLK, 512, PSMEM_BYTES>>>(Whh, out);

    write_final<<<(BB * HH + 255) / 256, 256>>>(out + (size_t)BB * SS * HH);
}

// round 15
// speedup vs baseline: 2.6340x; 1.1531x over previous
#include <cuda_runtime.h>
#include <cuda_fp16.h>
#include <math.h>
#include <stdint.h>

#define BB 64
#define SS 512
#define DD 1024
#define HH 1024
#define GG 4096   // 4*H
#define NBLK 128  // persistent blocks (1/SM via smem)

// Scratch (allocation-free rule: __device__ globals)
__device__ float g_xproj[(size_t)BB * SS * GG];  // [B*S, 4H], m = b*S + t (includes bih+bhh)
__device__ float g_h[2][BB * HH];                // ping-pong hidden state
__device__ float g_c[BB * HH];                   // cell state
__device__ unsigned int g_bar_count;             // grid barrier
__device__ volatile unsigned int g_bar_gen;
__device__ __half g_Xh[(size_t)BB * SS * DD];    // fp16 copy of inputs (67 MB)
__device__ __half g_Wh[(size_t)GG * DD];         // fp16 copy of Wih (8 MB)

__device__ __forceinline__ float sigmoidf_(float x) {
    return 1.0f / (1.0f + expf(-x));
}

__device__ __forceinline__ void cp16(uint32_t s, const void* g) {
    asm volatile("cp.async.cg.shared.global [%0], [%1], 16;\n" :: "r"(s), "l"(g));
}
#define CP_COMMIT() asm volatile("cp.async.commit_group;\n" ::: "memory")
#define CP_WAIT(N)  asm volatile("cp.async.wait_group %0;\n" :: "n"(N) : "memory")

#define MMA_TF32(C, A, B0, B1)                                               \
    asm volatile(                                                            \
        "mma.sync.aligned.m16n8k8.row.col.f32.tf32.tf32.f32 "                \
        "{%0,%1,%2,%3}, {%4,%5,%6,%7}, {%8,%9}, {%0,%1,%2,%3};\n"            \
        : "+f"((C)[0]), "+f"((C)[1]), "+f"((C)[2]), "+f"((C)[3])             \
        : "r"((A)[0]), "r"((A)[1]), "r"((A)[2]), "r"((A)[3]),                \
          "r"(B0), "r"(B1))

#define MMA_F16(C, A, B0, B1)                                                \
    asm volatile(                                                            \
        "mma.sync.aligned.m16n8k16.row.col.f32.f16.f16.f32 "                 \
        "{%0,%1,%2,%3}, {%4,%5,%6,%7}, {%8,%9}, {%0,%1,%2,%3};\n"            \
        : "+f"((C)[0]), "+f"((C)[1]), "+f"((C)[2]), "+f"((C)[3])             \
        : "r"((A)[0]), "r"((A)[1]), "r"((A)[2]), "r"((A)[3]),                \
          "r"(B0), "r"(B1))

// ---------------------------------------------------------------------------
__global__ void init_state(const float* __restrict__ h0, const float* __restrict__ c0) {
    int i = blockIdx.x * blockDim.x + threadIdx.x;
    if (i < BB * HH) {
        g_h[0][i] = h0[i];
        g_c[i]    = c0[i];
    }
}

// ---------------------------------------------------------------------------
// fp32 -> fp16 converters (vectorized: 4 elems/thread)
// ---------------------------------------------------------------------------
__global__ void cvt_x_fp16(const float* __restrict__ X) {
    size_t i = ((size_t)blockIdx.x * blockDim.x + threadIdx.x) * 4;
    if (i < (size_t)BB * SS * DD) {
        float4 v = *(const float4*)(X + i);
        __half2 lo = __floats2half2_rn(v.x, v.y);
        __half2 hi = __floats2half2_rn(v.z, v.w);
        *(__half2*)(g_Xh + i) = lo;
        *(__half2*)(g_Xh + i + 2) = hi;
    }
}
__global__ void cvt_w_fp16(const float* __restrict__ W) {
    size_t i = ((size_t)blockIdx.x * blockDim.x + threadIdx.x) * 4;
    if (i < (size_t)GG * DD) {
        float4 v = *(const float4*)(W + i);
        __half2 lo = __floats2half2_rn(v.x, v.y);
        __half2 hi = __floats2half2_rn(v.z, v.w);
        *(__half2*)(g_Wh + i) = lo;
        *(__half2*)(g_Wh + i + 2) = hi;
    }
}

// ---------------------------------------------------------------------------
// xproj (fp16 MMA, fp32 accum): C[32768, 4096] = X @ Wih^T + (bih + bhh)
// Block tile 256(M) x 128(N), 512 threads (16 warps), warp tile 64x32.
// K chunks of 64 halves (128B rows), double-buffered cp.async.
// m16n8k16: A frags a0/a1 = rows gid/gid+8 cols 2tg..2tg+1, a2/a3 = cols +8.
// ---------------------------------------------------------------------------
#define XBM 256
#define XBN 128
#define XBK 64                          // halves per K chunk
#define XSTRIDE 72                      // halves per smem row (64 + 8 pad)
#define XA_ELEMS (XBM * XSTRIDE)        // halves
#define XB_ELEMS (XBN * XSTRIDE)
#define XSMEM_BYTES ((2 * XA_ELEMS + 2 * XB_ELEMS) * 2)   // 110,592 B

__global__ __launch_bounds__(512) void xproj_mma(
    const float* __restrict__ bih,
    const float* __restrict__ bhh)
{
    extern __shared__ __half xsm[];
    __half* As = xsm;
    __half* Bs = xsm + 2 * XA_ELEMS;

    const int m0 = blockIdx.y * XBM;
    const int n0 = blockIdx.x * XBN;
    const int tid = threadIdx.x;
    const int wid = tid >> 5;
    const int lane = tid & 31;
    const int gid = lane >> 2;
    const int tg  = lane & 3;
    const int wm = wid & 3;      // m 64-rows
    const int wn = wid >> 2;     // n 32-cols

    const uint32_t As_s = (uint32_t)__cvta_generic_to_shared(As);
    const uint32_t Bs_s = (uint32_t)__cvta_generic_to_shared(Bs);

    // staging: unit = 16B = 8 halves. A: 256 rows x 8 units = 2048 -> 4/thread
    auto load_tiles = [&](int k0, int buf) {
#pragma unroll
        for (int i = 0; i < 4; i++) {
            int u = tid + i * 512;
            int r = u >> 3;
            int c8 = (u & 7) * 8;
            cp16(As_s + (uint32_t)((buf * XA_ELEMS + r * XSTRIDE + c8) * 2),
                 g_Xh + (size_t)(m0 + r) * DD + k0 + c8);
        }
#pragma unroll
        for (int i = 0; i < 2; i++) {             // B: 128x8 units = 1024
            int u = tid + i * 512;
            int r = u >> 3;
            int c8 = (u & 7) * 8;
            cp16(Bs_s + (uint32_t)((buf * XB_ELEMS + r * XSTRIDE + c8) * 2),
                 g_Wh + (size_t)(n0 + r) * DD + k0 + c8);
        }
    };

    float acc[4][4][4];
#pragma unroll
    for (int a = 0; a < 4; a++)
#pragma unroll
        for (int b = 0; b < 4; b++)
#pragma unroll
            for (int c = 0; c < 4; c++) acc[a][b][c] = 0.0f;

    load_tiles(0, 0);
    CP_COMMIT();

#pragma unroll 1
    for (int kc = 0; kc < DD / XBK; kc++) {
        int cur = kc & 1;
        if (kc + 1 < DD / XBK) {
            load_tiles((kc + 1) * XBK, cur ^ 1);
            CP_COMMIT();
            CP_WAIT(1);
        } else {
            CP_WAIT(0);
        }
        __syncthreads();

        const __half* ab = As + cur * XA_ELEMS;
        const __half* bb = Bs + cur * XB_ELEMS;

#pragma unroll
        for (int ks = 0; ks < XBK / 16; ks++) {   // 4 k16 steps
            int kb = ks * 16 + 2 * tg;
            uint32_t af[4][4];
#pragma unroll
            for (int mi = 0; mi < 4; mi++) {
                int row = wm * 64 + mi * 16 + gid;
                af[mi][0] = *(const uint32_t*)&ab[row * XSTRIDE + kb];
                af[mi][1] = *(const uint32_t*)&ab[(row + 8) * XSTRIDE + kb];
                af[mi][2] = *(const uint32_t*)&ab[row * XSTRIDE + kb + 8];
                af[mi][3] = *(const uint32_t*)&ab[(row + 8) * XSTRIDE + kb + 8];
            }
#pragma unroll
            for (int ni = 0; ni < 4; ni++) {
                int nrow = wn * 32 + ni * 8 + gid;
                uint32_t b0 = *(const uint32_t*)&bb[nrow * XSTRIDE + kb];
                uint32_t b1 = *(const uint32_t*)&bb[nrow * XSTRIDE + kb + 8];
#pragma unroll
                for (int mi = 0; mi < 4; mi++) MMA_F16(acc[mi][ni], af[mi], b0, b1);
            }
        }
        __syncthreads();
    }

#pragma unroll
    for (int ni = 0; ni < 4; ni++) {
        int n = n0 + wn * 32 + ni * 8 + tg * 2;
        float bv0 = bih[n] + bhh[n];
        float bv1 = bih[n + 1] + bhh[n + 1];
#pragma unroll
        for (int mi = 0; mi < 4; mi++) {
            int m = m0 + wm * 64 + mi * 16 + gid;
            float2 v0 = make_float2(acc[mi][ni][0] + bv0, acc[mi][ni][1] + bv1);
            *(float2*)(g_xproj + (size_t)m * GG + n) = v0;
            float2 v1 = make_float2(acc[mi][ni][2] + bv0, acc[mi][ni][3] + bv1);
            *(float2*)(g_xproj + (size_t)(m + 8) * GG + n) = v1;
        }
    }
}

// ---------------------------------------------------------------------------
// Persistent LSTM (R8 winner, untouched). 128 blocks, 1/SM, 512 threads.
// Block bx: j-cols [bx*8, bx*8+8), all 64 batches, 4 gates (32 Whh rows).
// 16 warps = 4 m-tiles x 2 gate-halves x 2 K-halves (partial sums in 2 slabs).
// ---------------------------------------------------------------------------
#define WS_STRIDE 1028
#define WS_TOT (32 * WS_STRIDE)
#define NCH 8
#define HS_STRIDE 132
#define HS_ELEMS (64 * HS_STRIDE)
#define GSM_ELEMS (2 * 4 * 64 * 8)
#define CSM_ELEMS 512
#define PSMEM_FLOATS (WS_TOT + 2 * HS_ELEMS + GSM_ELEMS + CSM_ELEMS)
#define PSMEM_BYTES (PSMEM_FLOATS * 4)  // 217,600 B

__device__ __forceinline__ void grid_barrier(int tid) {
    __threadfence();
    __syncthreads();
    if (tid == 0) {
        unsigned int gen = g_bar_gen;
        if (atomicAdd(&g_bar_count, 1) == NBLK - 1) {
            g_bar_count = 0;
            __threadfence();
            g_bar_gen = gen + 1;
        } else {
            while (g_bar_gen == gen) { }
        }
    }
    __syncthreads();
}

__global__ __launch_bounds__(512, 1) void lstm_persist(
    const float* __restrict__ Whh,
    float* __restrict__ out)
{
    extern __shared__ float sm[];
    float* ws  = sm;                         // [32][WS_STRIDE] weights (persistent)
    float* hs  = ws + WS_TOT;                // [2][64][HS_STRIDE] h chunks
    float* gsm = hs + 2 * HS_ELEMS;          // [2][4][64][8] gate partials
    float* csm = gsm + GSM_ELEMS;            // [512] cell slice (persistent)

    const int j0  = blockIdx.x * 8;
    const int tid = threadIdx.x;
    const int wid = tid >> 5;
    const int lane = tid & 31;
    const int gid = lane >> 2;
    const int tg  = lane & 3;
    const int mt = wid & 3;            // m-tile (16 batches)
    const int gh = (wid >> 2) & 1;     // gate half
    const int kh = wid >> 3;           // K half (0: k<512, 1: k>=512)

    const uint32_t ws_s = (uint32_t)__cvta_generic_to_shared(ws);
    const uint32_t hs_s = (uint32_t)__cvta_generic_to_shared(hs);

    // ---- one-time: load Whh slice (32 rows x 1024) into SMEM ----
#pragma unroll 4
    for (int i = 0; i < 16; i++) {
        int u = tid + i * 512;               // 0..8191 16B-units
        int r = u >> 8;                      // row = g*8 + jj
        int c4 = (u & 255) * 4;
        int n = (r >> 3) * HH + j0 + (r & 7);
        cp16(ws_s + (uint32_t)(r * WS_STRIDE + c4) * 4, Whh + (size_t)n * HH + c4);
    }
    CP_COMMIT();

    // ---- one-time: load c slice, precompute epilogue indices (1 elem/thread) ----
    const int b_e  = tid >> 3;
    const int jj_e = tid & 7;
    const int nj_e = j0 + jj_e;
    const size_t xb_e = (size_t)b_e * SS * GG + nj_e;
    const size_t ob_e = (size_t)b_e * SS * HH + nj_e;
    csm[tid] = g_c[b_e * HH + nj_e];
    CP_WAIT(0);
    __syncthreads();

    const float* wb0 = ws + (size_t)((gh * 2) * 8 + gid) * WS_STRIDE + kh * 512;
    const float* wb1 = ws + (size_t)((gh * 2 + 1) * 8 + gid) * WS_STRIDE + kh * 512;
    const int arow0 = mt * 16 + gid;
    const int kloc = kh * 64;          // this warp's column base inside hs buffer

#pragma unroll 1
    for (int t = 0; t < SS; t++) {
        const float* __restrict__ h_in = g_h[t & 1];
        float* __restrict__ h_out = g_h[(t + 1) & 1];

        // chunk c: hs cols 0-63 <- h[k= c*64 ..), cols 64-127 <- h[k= 512+c*64 ..)
        auto issue_h = [&](int c, int buf) {
#pragma unroll
            for (int i = 0; i < 4; i++) {
                int u = tid + i * 512;          // 0..2047 units
                int row = u >> 5;
                int c4 = (u & 31) * 4;          // 0..124
                int gk = (c4 < 64) ? (c * 64 + c4) : (512 + c * 64 + (c4 - 64));
                cp16(hs_s + (uint32_t)(buf * HS_ELEMS + row * HS_STRIDE + c4) * 4,
                     h_in + (size_t)row * HH + gk);
            }
        };

        issue_h(0, 0);
        CP_COMMIT();

        // prefetch xproj gate tile for this (block, t): 4 scalars/thread
        float xp[4];
#pragma unroll
        for (int g = 0; g < 4; g++)
            xp[g] = __ldg(&g_xproj[xb_e + (size_t)t * GG + g * HH]);

        float c0[4] = {0.f, 0.f, 0.f, 0.f};
        float c1[4] = {0.f, 0.f, 0.f, 0.f};

#pragma unroll 1
        for (int c = 0; c < NCH; c++) {
            int cur = c & 1;
            if (c + 1 < NCH) {
                issue_h(c + 1, cur ^ 1);
                CP_COMMIT();
                CP_WAIT(1);
            } else {
                CP_WAIT(0);
            }
            __syncthreads();

            const float* hb = hs + cur * HS_ELEMS;
            const int kg = c * 64;             // k offset within this warp's K-half

#pragma unroll
            for (int ks = 0; ks < 8; ks++) {
                int kb = kloc + ks * 8;
                uint32_t a[4];
                a[0] = __float_as_uint(hb[(arow0)     * HS_STRIDE + kb + tg]);
                a[1] = __float_as_uint(hb[(arow0 + 8) * HS_STRIDE + kb + tg]);
                a[2] = __float_as_uint(hb[(arow0)     * HS_STRIDE + kb + tg + 4]);
                a[3] = __float_as_uint(hb[(arow0 + 8) * HS_STRIDE + kb + tg + 4]);

                uint32_t b00 = __float_as_uint(wb0[kg + ks * 8 + tg]);
                uint32_t b01 = __float_as_uint(wb0[kg + ks * 8 + tg + 4]);
                MMA_TF32(c0, a, b00, b01);

                uint32_t b10 = __float_as_uint(wb1[kg + ks * 8 + tg]);
                uint32_t b11 = __float_as_uint(wb1[kg + ks * 8 + tg + 4]);
                MMA_TF32(c1, a, b10, b11);
            }
            __syncthreads();
        }

        // stash partials: gsm[kh][g][batch][jj]
        {
            int g0 = gh * 2;
            int r0 = mt * 16 + gid;
            float* gs = gsm + kh * (4 * 64 * 8);
            gs[(g0 * 64 + r0)     * 8 + tg * 2 + 0] = c0[0];
            gs[(g0 * 64 + r0)     * 8 + tg * 2 + 1] = c0[1];
            gs[(g0 * 64 + r0 + 8) * 8 + tg * 2 + 0] = c0[2];
            gs[(g0 * 64 + r0 + 8) * 8 + tg * 2 + 1] = c0[3];
            int g1 = g0 + 1;
            gs[(g1 * 64 + r0)     * 8 + tg * 2 + 0] = c1[0];
            gs[(g1 * 64 + r0)     * 8 + tg * 2 + 1] = c1[1];
            gs[(g1 * 64 + r0 + 8) * 8 + tg * 2 + 0] = c1[2];
            gs[(g1 * 64 + r0 + 8) * 8 + tg * 2 + 1] = c1[3];
        }
        __syncthreads();

        // fused cell update (1 element per thread; sum the two K-half slabs)
        {
            const float* s0 = gsm;
            const float* s1 = gsm + (4 * 64 * 8);
            int base = b_e * 8 + jj_e;

            float gi = s0[(0 * 64) * 8 + base] + s1[(0 * 64) * 8 + base] + xp[0];
            float gf = s0[(1 * 64) * 8 + base] + s1[(1 * 64) * 8 + base] + xp[1];
            float gg = s0[(2 * 64) * 8 + base] + s1[(2 * 64) * 8 + base] + xp[2];
            float go = s0[(3 * 64) * 8 + base] + s1[(3 * 64) * 8 + base] + xp[3];

            float iv = sigmoidf_(gi);
            float fv = sigmoidf_(gf);
            float gv = tanhf(gg);
            float ov = sigmoidf_(go);

            float cc = fv * csm[tid] + iv * gv;
            csm[tid] = cc;
            float h = ov * tanhf(cc);
            h_out[b_e * HH + nj_e] = h;
            out[ob_e + (size_t)t * HH] = h;
        }

        grid_barrier(tid);
    }

    // write back cell state
    g_c[b_e * HH + nj_e] = csm[tid];
}

// ---------------------------------------------------------------------------
__global__ void write_final(float* __restrict__ tail) {
    int i = blockIdx.x * blockDim.x + threadIdx.x;
    if (i < BB * HH) {
        tail[i] = g_h[SS & 1][i];
        tail[BB * HH + i] = g_c[i];
    }
}

// ---------------------------------------------------------------------------
extern "C" void kernel_launch(void* const* d_in, const int* in_sizes, int n_in,
                              void* d_out, int out_size) {
    const float* X   = (const float*)d_in[0];  // [B,S,D]
    const float* h0  = (const float*)d_in[1];  // [1,B,H]
    const float* c0  = (const float*)d_in[2];  // [1,B,H]
    const float* Wih = (const float*)d_in[3];  // [4H,D]
    const float* Whh = (const float*)d_in[4];  // [4H,H]
    const float* bih = (const float*)d_in[5];  // [4H]
    const float* bhh = (const float*)d_in[6];  // [4H]
    float* out = (float*)d_out;                // outputs [B,S,H] | hn | cn

    cudaFuncSetAttribute(xproj_mma,
                         cudaFuncAttributeMaxDynamicSharedMemorySize, XSMEM_BYTES);
    cudaFuncSetAttribute(lstm_persist,
                         cudaFuncAttributeMaxDynamicSharedMemorySize, PSMEM_BYTES);

    init_state<<<(BB * HH + 255) / 256, 256>>>(h0, c0);

    cvt_x_fp16<<<(int)(((size_t)BB * SS * DD / 4 + 255) / 256), 256>>>(X);
    cvt_w_fp16<<<(int)(((size_t)GG * DD / 4 + 255) / 256), 256>>>(Wih);

    dim3 gx(GG / XBN, (BB * SS) / XBM);
    xproj_mma<<<gx, 512, XSMEM_BYTES>>>(bih, bhh);

    lstm_persist<<<NBLK, 512, PSMEM_BYTES>>>(Whh, out);

    write_final<<<(BB * HH + 255) / 256, 256>>>(out + (size_t)BB * SS * HH);
}

// round 16
// speedup vs baseline: 3.5866x; 1.3617x over previous
#include <cuda_runtime.h>
#include <cuda_fp16.h>
#include <math.h>
#include <stdint.h>

#define BB 64
#define SS 512
#define DD 1024
#define HH 1024
#define GG 4096   // 4*H
#define NBLK 128  // persistent blocks (1/SM via smem)

// Scratch (allocation-free rule: __device__ globals)
__device__ float g_xproj[(size_t)BB * SS * GG];  // [B*S, 4H], m = b*S + t (includes bih+bhh)
__device__ __half g_h[2][BB * HH];               // ping-pong hidden state (fp16)
__device__ float g_c[BB * HH];                   // cell state (fp32)
__device__ unsigned int g_bar_count;             // grid barrier
__device__ volatile unsigned int g_bar_gen;
__device__ __half g_Xh[(size_t)BB * SS * DD];    // fp16 copy of inputs (67 MB)
__device__ __half g_Wh[(size_t)GG * DD];         // fp16 copy of Wih (8 MB)
__device__ __half g_Whh_h[(size_t)GG * HH];      // fp16 copy of Whh (8 MB)

__device__ __forceinline__ float sigmoidf_(float x) {
    return 1.0f / (1.0f + expf(-x));
}

__device__ __forceinline__ void cp16(uint32_t s, const void* g) {
    asm volatile("cp.async.cg.shared.global [%0], [%1], 16;\n" :: "r"(s), "l"(g));
}
#define CP_COMMIT() asm volatile("cp.async.commit_group;\n" ::: "memory")
#define CP_WAIT(N)  asm volatile("cp.async.wait_group %0;\n" :: "n"(N) : "memory")

#define MMA_F16(C, A, B0, B1)                                                \
    asm volatile(                                                            \
        "mma.sync.aligned.m16n8k16.row.col.f32.f16.f16.f32 "                 \
        "{%0,%1,%2,%3}, {%4,%5,%6,%7}, {%8,%9}, {%0,%1,%2,%3};\n"            \
        : "+f"((C)[0]), "+f"((C)[1]), "+f"((C)[2]), "+f"((C)[3])             \
        : "r"((A)[0]), "r"((A)[1]), "r"((A)[2]), "r"((A)[3]),                \
          "r"(B0), "r"(B1))

// ---------------------------------------------------------------------------
__global__ void init_state(const float* __restrict__ h0, const float* __restrict__ c0) {
    int i = blockIdx.x * blockDim.x + threadIdx.x;
    if (i < BB * HH) {
        g_h[0][i] = __float2half_rn(h0[i]);
        g_c[i]    = c0[i];
    }
}

// ---------------------------------------------------------------------------
// fp32 -> fp16 converters (vectorized: 4 elems/thread)
// ---------------------------------------------------------------------------
__global__ void cvt_x_fp16(const float* __restrict__ X) {
    size_t i = ((size_t)blockIdx.x * blockDim.x + threadIdx.x) * 4;
    if (i < (size_t)BB * SS * DD) {
        float4 v = *(const float4*)(X + i);
        *(__half2*)(g_Xh + i)     = __floats2half2_rn(v.x, v.y);
        *(__half2*)(g_Xh + i + 2) = __floats2half2_rn(v.z, v.w);
    }
}
__global__ void cvt_w_fp16(const float* __restrict__ W) {
    size_t i = ((size_t)blockIdx.x * blockDim.x + threadIdx.x) * 4;
    if (i < (size_t)GG * DD) {
        float4 v = *(const float4*)(W + i);
        *(__half2*)(g_Wh + i)     = __floats2half2_rn(v.x, v.y);
        *(__half2*)(g_Wh + i + 2) = __floats2half2_rn(v.z, v.w);
    }
}
__global__ void cvt_whh_fp16(const float* __restrict__ W) {
    size_t i = ((size_t)blockIdx.x * blockDim.x + threadIdx.x) * 4;
    if (i < (size_t)GG * HH) {
        float4 v = *(const float4*)(W + i);
        *(__half2*)(g_Whh_h + i)     = __floats2half2_rn(v.x, v.y);
        *(__half2*)(g_Whh_h + i + 2) = __floats2half2_rn(v.z, v.w);
    }
}

// ---------------------------------------------------------------------------
// xproj (fp16 MMA, fp32 accum): C[32768, 4096] = X @ Wih^T + (bih + bhh)
// Block tile 256(M) x 128(N), 512 threads (16 warps), warp tile 64x32.
// ---------------------------------------------------------------------------
#define XBM 256
#define XBN 128
#define XBK 64                          // halves per K chunk
#define XSTRIDE 72                      // halves per smem row (64 + 8 pad)
#define XA_ELEMS (XBM * XSTRIDE)
#define XB_ELEMS (XBN * XSTRIDE)
#define XSMEM_BYTES ((2 * XA_ELEMS + 2 * XB_ELEMS) * 2)   // 110,592 B

__global__ __launch_bounds__(512) void xproj_mma(
    const float* __restrict__ bih,
    const float* __restrict__ bhh)
{
    extern __shared__ __half xsm[];
    __half* As = xsm;
    __half* Bs = xsm + 2 * XA_ELEMS;

    const int m0 = blockIdx.y * XBM;
    const int n0 = blockIdx.x * XBN;
    const int tid = threadIdx.x;
    const int wid = tid >> 5;
    const int lane = tid & 31;
    const int gid = lane >> 2;
    const int tg  = lane & 3;
    const int wm = wid & 3;      // m 64-rows
    const int wn = wid >> 2;     // n 32-cols

    const uint32_t As_s = (uint32_t)__cvta_generic_to_shared(As);
    const uint32_t Bs_s = (uint32_t)__cvta_generic_to_shared(Bs);

    auto load_tiles = [&](int k0, int buf) {
#pragma unroll
        for (int i = 0; i < 4; i++) {
            int u = tid + i * 512;
            int r = u >> 3;
            int c8 = (u & 7) * 8;
            cp16(As_s + (uint32_t)((buf * XA_ELEMS + r * XSTRIDE + c8) * 2),
                 g_Xh + (size_t)(m0 + r) * DD + k0 + c8);
        }
#pragma unroll
        for (int i = 0; i < 2; i++) {
            int u = tid + i * 512;
            int r = u >> 3;
            int c8 = (u & 7) * 8;
            cp16(Bs_s + (uint32_t)((buf * XB_ELEMS + r * XSTRIDE + c8) * 2),
                 g_Wh + (size_t)(n0 + r) * DD + k0 + c8);
        }
    };

    float acc[4][4][4];
#pragma unroll
    for (int a = 0; a < 4; a++)
#pragma unroll
        for (int b = 0; b < 4; b++)
#pragma unroll
            for (int c = 0; c < 4; c++) acc[a][b][c] = 0.0f;

    load_tiles(0, 0);
    CP_COMMIT();

#pragma unroll 1
    for (int kc = 0; kc < DD / XBK; kc++) {
        int cur = kc & 1;
        if (kc + 1 < DD / XBK) {
            load_tiles((kc + 1) * XBK, cur ^ 1);
            CP_COMMIT();
            CP_WAIT(1);
        } else {
            CP_WAIT(0);
        }
        __syncthreads();

        const __half* ab = As + cur * XA_ELEMS;
        const __half* bb = Bs + cur * XB_ELEMS;

#pragma unroll
        for (int ks = 0; ks < XBK / 16; ks++) {
            int kb = ks * 16 + 2 * tg;
            uint32_t af[4][4];
#pragma unroll
            for (int mi = 0; mi < 4; mi++) {
                int row = wm * 64 + mi * 16 + gid;
                af[mi][0] = *(const uint32_t*)&ab[row * XSTRIDE + kb];
                af[mi][1] = *(const uint32_t*)&ab[(row + 8) * XSTRIDE + kb];
                af[mi][2] = *(const uint32_t*)&ab[row * XSTRIDE + kb + 8];
                af[mi][3] = *(const uint32_t*)&ab[(row + 8) * XSTRIDE + kb + 8];
            }
#pragma unroll
            for (int ni = 0; ni < 4; ni++) {
                int nrow = wn * 32 + ni * 8 + gid;
                uint32_t b0 = *(const uint32_t*)&bb[nrow * XSTRIDE + kb];
                uint32_t b1 = *(const uint32_t*)&bb[nrow * XSTRIDE + kb + 8];
#pragma unroll
                for (int mi = 0; mi < 4; mi++) MMA_F16(acc[mi][ni], af[mi], b0, b1);
            }
        }
        __syncthreads();
    }

#pragma unroll
    for (int ni = 0; ni < 4; ni++) {
        int n = n0 + wn * 32 + ni * 8 + tg * 2;
        float bv0 = bih[n] + bhh[n];
        float bv1 = bih[n + 1] + bhh[n + 1];
#pragma unroll
        for (int mi = 0; mi < 4; mi++) {
            int m = m0 + wm * 64 + mi * 16 + gid;
            float2 v0 = make_float2(acc[mi][ni][0] + bv0, acc[mi][ni][1] + bv1);
            *(float2*)(g_xproj + (size_t)m * GG + n) = v0;
            float2 v1 = make_float2(acc[mi][ni][2] + bv0, acc[mi][ni][3] + bv1);
            *(float2*)(g_xproj + (size_t)(m + 8) * GG + n) = v1;
        }
    }
}

// ---------------------------------------------------------------------------
// Persistent LSTM (R8 structure, fp16 operands). 128 blocks, 512 threads.
// Block bx: j-cols [bx*8, bx*8+8), all 64 batches, 4 gates (32 Whh rows).
// 16 warps = 4 m-tiles x 2 gate-halves x 2 K-halves; m16n8k16 fp16 MMA,
// fp32 accum; Whh fp16 in SMEM (loaded once), h ring fp16, cell math fp32.
// ---------------------------------------------------------------------------
#define WSTRH 1032                      // halves per weight row (1024 + 8 pad)
#define WS_TOTH (32 * WSTRH)            // 33024 halves
#define NCH 8
#define HSTRH 136                       // halves per staged h row (128 + 8 pad)
#define HS_ELEMSH (64 * HSTRH)          // 8704 halves per buffer
#define GSM_ELEMS (2 * 4 * 64 * 8)      // fp32
#define CSM_ELEMS 512
#define PSMEM_BYTES ((WS_TOTH + 2 * HS_ELEMSH) * 2 + (GSM_ELEMS + CSM_ELEMS) * 4)  // 119,296 B

__device__ __forceinline__ void grid_barrier(int tid) {
    __threadfence();
    __syncthreads();
    if (tid == 0) {
        unsigned int gen = g_bar_gen;
        if (atomicAdd(&g_bar_count, 1) == NBLK - 1) {
            g_bar_count = 0;
            __threadfence();
            g_bar_gen = gen + 1;
        } else {
            while (g_bar_gen == gen) { }
        }
    }
    __syncthreads();
}

__global__ __launch_bounds__(512, 1) void lstm_persist(float* __restrict__ out)
{
    extern __shared__ __half smh[];
    __half* ws = smh;                          // [32][WSTRH] weights (persistent)
    __half* hs = smh + WS_TOTH;                // [2][64][HSTRH] h chunks
    float* gsm = (float*)(smh + WS_TOTH + 2 * HS_ELEMSH);  // [2][4][64][8]
    float* csm = gsm + GSM_ELEMS;              // [512] cell slice

    const int j0  = blockIdx.x * 8;
    const int tid = threadIdx.x;
    const int wid = tid >> 5;
    const int lane = tid & 31;
    const int gid = lane >> 2;
    const int tg  = lane & 3;
    const int mt = wid & 3;            // m-tile (16 batches)
    const int gh = (wid >> 2) & 1;     // gate half
    const int kh = wid >> 3;           // K half (0: k<512, 1: k>=512)

    const uint32_t ws_s = (uint32_t)__cvta_generic_to_shared(ws);
    const uint32_t hs_s = (uint32_t)__cvta_generic_to_shared(hs);

    // ---- one-time: load Whh slice (32 rows x 1024 halves = 64KB) ----
#pragma unroll 4
    for (int i = 0; i < 8; i++) {
        int u = tid + i * 512;               // 0..4095 16B-units
        int r = u >> 7;                      // row = g*8 + jj
        int c8 = (u & 127) * 8;
        int n = (r >> 3) * HH + j0 + (r & 7);
        cp16(ws_s + (uint32_t)((r * WSTRH + c8) * 2), g_Whh_h + (size_t)n * HH + c8);
    }
    CP_COMMIT();

    // ---- one-time: cell slice + epilogue indices (1 elem/thread) ----
    const int b_e  = tid >> 3;
    const int jj_e = tid & 7;
    const int nj_e = j0 + jj_e;
    const size_t xb_e = (size_t)b_e * SS * GG + nj_e;
    const size_t ob_e = (size_t)b_e * SS * HH + nj_e;
    csm[tid] = g_c[b_e * HH + nj_e];
    CP_WAIT(0);
    __syncthreads();

    const __half* wb0 = ws + (size_t)((gh * 2) * 8 + gid) * WSTRH + kh * 512 + 2 * tg;
    const __half* wb1 = ws + (size_t)((gh * 2 + 1) * 8 + gid) * WSTRH + kh * 512 + 2 * tg;
    const int arow0 = mt * 16 + gid;
    const int kloc = kh * 64;          // warp's col base inside staged 128-col buffer

#pragma unroll 1
    for (int t = 0; t < SS; t++) {
        const __half* __restrict__ h_in = g_h[t & 1];
        __half* __restrict__ h_out = g_h[(t + 1) & 1];

        // chunk c: hs cols 0-63 <- h[c*64 ..), cols 64-127 <- h[512 + c*64 ..)
        auto issue_h = [&](int c, int buf) {
#pragma unroll
            for (int i = 0; i < 2; i++) {
                int u = tid + i * 512;          // 0..1023 16B-units
                int row = u >> 4;               // 16 units per 128-half row
                int c8 = (u & 15) * 8;          // 0..120
                int gk = (c8 < 64) ? (c * 64 + c8) : (512 + c * 64 + (c8 - 64));
                cp16(hs_s + (uint32_t)((buf * HS_ELEMSH + row * HSTRH + c8) * 2),
                     h_in + (size_t)row * HH + gk);
            }
        };

        issue_h(0, 0);
        CP_COMMIT();

        // prefetch xproj gate tile for this (block, t): 4 scalars/thread
        float xp[4];
#pragma unroll
        for (int g = 0; g < 4; g++)
            xp[g] = __ldg(&g_xproj[xb_e + (size_t)t * GG + g * HH]);

        float c0[4] = {0.f, 0.f, 0.f, 0.f};
        float c1[4] = {0.f, 0.f, 0.f, 0.f};

#pragma unroll 1
        for (int c = 0; c < NCH; c++) {
            int cur = c & 1;
            if (c + 1 < NCH) {
                issue_h(c + 1, cur ^ 1);
                CP_COMMIT();
                CP_WAIT(1);
            } else {
                CP_WAIT(0);
            }
            __syncthreads();

            const __half* hb = hs + cur * HS_ELEMSH;
            const int kg = c * 64;             // k offset within warp's K-half

#pragma unroll
            for (int ks = 0; ks < 4; ks++) {   // 4 k16 steps per 64-col chunk
                int kb = kloc + ks * 16 + 2 * tg;
                uint32_t a[4];
                a[0] = *(const uint32_t*)&hb[(arow0)     * HSTRH + kb];
                a[1] = *(const uint32_t*)&hb[(arow0 + 8) * HSTRH + kb];
                a[2] = *(const uint32_t*)&hb[(arow0)     * HSTRH + kb + 8];
                a[3] = *(const uint32_t*)&hb[(arow0 + 8) * HSTRH + kb + 8];

                uint32_t b00 = *(const uint32_t*)&wb0[kg + ks * 16];
                uint32_t b01 = *(const uint32_t*)&wb0[kg + ks * 16 + 8];
                MMA_F16(c0, a, b00, b01);

                uint32_t b10 = *(const uint32_t*)&wb1[kg + ks * 16];
                uint32_t b11 = *(const uint32_t*)&wb1[kg + ks * 16 + 8];
                MMA_F16(c1, a, b10, b11);
            }
            __syncthreads();
        }

        // stash partials: gsm[kh][g][batch][jj]
        {
            int g0 = gh * 2;
            int r0 = mt * 16 + gid;
            float* gs = gsm + kh * (4 * 64 * 8);
            gs[(g0 * 64 + r0)     * 8 + tg * 2 + 0] = c0[0];
            gs[(g0 * 64 + r0)     * 8 + tg * 2 + 1] = c0[1];
            gs[(g0 * 64 + r0 + 8) * 8 + tg * 2 + 0] = c0[2];
            gs[(g0 * 64 + r0 + 8) * 8 + tg * 2 + 1] = c0[3];
            int g1 = g0 + 1;
            gs[(g1 * 64 + r0)     * 8 + tg * 2 + 0] = c1[0];
            gs[(g1 * 64 + r0)     * 8 + tg * 2 + 1] = c1[1];
            gs[(g1 * 64 + r0 + 8) * 8 + tg * 2 + 0] = c1[2];
            gs[(g1 * 64 + r0 + 8) * 8 + tg * 2 + 1] = c1[3];
        }
        __syncthreads();

        // fused cell update (1 element per thread; sum the two K-half slabs)
        {
            const float* s0 = gsm;
            const float* s1 = gsm + (4 * 64 * 8);
            int base = b_e * 8 + jj_e;

            float gi = s0[(0 * 64) * 8 + base] + s1[(0 * 64) * 8 + base] + xp[0];
            float gf = s0[(1 * 64) * 8 + base] + s1[(1 * 64) * 8 + base] + xp[1];
            float gg = s0[(2 * 64) * 8 + base] + s1[(2 * 64) * 8 + base] + xp[2];
            float go = s0[(3 * 64) * 8 + base] + s1[(3 * 64) * 8 + base] + xp[3];

            float iv = sigmoidf_(gi);
            float fv = sigmoidf_(gf);
            float gv = tanhf(gg);
            float ov = sigmoidf_(go);

            float cc = fv * csm[tid] + iv * gv;
            csm[tid] = cc;
            float h = ov * tanhf(cc);
            h_out[b_e * HH + nj_e] = __float2half_rn(h);
            out[ob_e + (size_t)t * HH] = h;
        }

        grid_barrier(tid);
    }

    // write back cell state
    g_c[b_e * HH + nj_e] = csm[tid];
}

// ---------------------------------------------------------------------------
// tail: hn = outputs[:,511,:] (exact fp32 h), cn = g_c
// ---------------------------------------------------------------------------
__global__ void write_final(float* __restrict__ out) {
    int i = blockIdx.x * blockDim.x + threadIdx.x;
    if (i < BB * HH) {
        int b = i >> 10, j = i & 1023;
        float* tail = out + (size_t)BB * SS * HH;
        tail[i] = out[((size_t)b * SS + (SS - 1)) * HH + j];
        tail[BB * HH + i] = g_c[i];
    }
}

// ---------------------------------------------------------------------------
extern "C" void kernel_launch(void* const* d_in, const int* in_sizes, int n_in,
                              void* d_out, int out_size) {
    const float* X   = (const float*)d_in[0];  // [B,S,D]
    const float* h0  = (const float*)d_in[1];  // [1,B,H]
    const float* c0  = (const float*)d_in[2];  // [1,B,H]
    const float* Wih = (const float*)d_in[3];  // [4H,D]
    const float* Whh = (const float*)d_in[4];  // [4H,H]
    const float* bih = (const float*)d_in[5];  // [4H]
    const float* bhh = (const float*)d_in[6];  // [4H]
    float* out = (float*)d_out;                // outputs [B,S,H] | hn | cn

    cudaFuncSetAttribute(xproj_mma,
                         cudaFuncAttributeMaxDynamicSharedMemorySize, XSMEM_BYTES);
    cudaFuncSetAttribute(lstm_persist,
                         cudaFuncAttributeMaxDynamicSharedMemorySize, PSMEM_BYTES);

    init_state<<<(BB * HH + 255) / 256, 256>>>(h0, c0);

    cvt_x_fp16<<<(int)(((size_t)BB * SS * DD / 4 + 255) / 256), 256>>>(X);
    cvt_w_fp16<<<(int)(((size_t)GG * DD / 4 + 255) / 256), 256>>>(Wih);
    cvt_whh_fp16<<<(int)(((size_t)GG * HH / 4 + 255) / 256), 256>>>(Whh);

    dim3 gx(GG / XBN, (BB * SS) / XBM);
    xproj_mma<<<gx, 512, XSMEM_BYTES>>>(bih, bhh);

    lstm_persist<<<NBLK, 512, PSMEM_BYTES>>>(out);

    write_final<<<(BB * HH + 255) / 256, 256>>>(out);
}